// round 3
// baseline (speedup 1.0000x reference)
#include <cuda_runtime.h>
#include <math.h>

#define EMB 256
#define NH1 32
#define NH2 16
#define MAXDAGS 1024
#define MAXOPS  102400

// ---------------- scratch (device globals; no allocation allowed) ----------------
__device__ int   g_offsets[MAXDAGS + 1];
__device__ int   g_dagid[MAXOPS];
__device__ float g_yzop[MAXDAGS * NH1];
__device__ float g_prpre[MAXDAGS * NH1];
__device__ float g_zop[NH1];
__device__ float g_zpr[NH1];
__device__ float g_partial[1024];
__device__ float g_inv;
__device__ unsigned int g_counter;

// ---------------- f32x2 helpers (sm_100+ packed FMA) ----------------
__device__ __forceinline__ void ffma2(unsigned long long& d, unsigned long long a, unsigned long long b) {
    asm("fma.rn.f32x2 %0, %1, %2, %0;" : "+l"(d) : "l"(a), "l"(b));
}
__device__ __forceinline__ unsigned long long pack2(float x, float y) {
    unsigned long long r;
    asm("mov.b64 %0, {%1,%2};" : "=l"(r) : "f"(x), "f"(y));
    return r;
}
__device__ __forceinline__ float2 unpack2(unsigned long long v) {
    float2 r;
    asm("mov.b64 {%0,%1}, %2;" : "=f"(r.x), "=f"(r.y) : "l"(v));
    return r;
}

// ================= kernel A: block0 = prefix scan (+counter reset), block1 = z-dots =================
__global__ void __launch_bounds__(1024) k_A(
    const int* __restrict__ num_ops, const float* __restrict__ z,
    const float* __restrict__ opW1, const float* __restrict__ opb1,
    const float* __restrict__ prW1, const float* __restrict__ prb1, int D)
{
    __shared__ int s[1024];
    __shared__ float sz[EMB];
    int t = threadIdx.x;
    if (blockIdx.x == 0) {
        if (t == 0) g_counter = 0u;
        int v = (t < D) ? num_ops[t] : 0;
        s[t] = v;
        __syncthreads();
        for (int off = 1; off < 1024; off <<= 1) {
            int u = (t >= off) ? s[t - off] : 0;
            __syncthreads();
            s[t] += u;
            __syncthreads();
        }
        g_offsets[t + 1] = s[t];
        if (t == 0) g_offsets[0] = 0;
    } else {
        for (int i = t; i < EMB; i += 1024) sz[i] = z[i];
        __syncthreads();
        if (t < 64) {
            int j = t & 31;
            const float* W = (t < 32) ? (opW1 + 2 * EMB * NH1) : (prW1 + (1 + EMB) * NH1);
            float a0 = 0.f, a1 = 0.f, a2 = 0.f, a3 = 0.f;
            for (int k = 0; k < EMB; k += 4) {
                a0 += sz[k + 0] * W[(k + 0) * NH1 + j];
                a1 += sz[k + 1] * W[(k + 1) * NH1 + j];
                a2 += sz[k + 2] * W[(k + 2) * NH1 + j];
                a3 += sz[k + 3] * W[(k + 3) * NH1 + j];
            }
            float a = (a0 + a1) + (a2 + a3);
            if (t < 32) g_zop[j] = a + opb1[j];
            else        g_zpr[j] = a + prb1[j];
        }
    }
}

// ================= kernel B: blocks [0,D) = fill dag ids, rest = per-dag y-dots =================
__global__ void __launch_bounds__(512) k_B(
    const float* __restrict__ y,
    const float* __restrict__ opW1, const float* __restrict__ prW1,
    int D, int N, int nb16)
{
    __shared__ float sy[16 * EMB];   // 16 KB
    __shared__ float sw[64 * NH1];   // 8 KB
    int t = threadIdx.x;
    if ((int)blockIdx.x < D) {
        int d = blockIdx.x;
        int s = g_offsets[d];
        int e = g_offsets[d + 1];
        if (d == D - 1) e = N;                 // pad-with-last semantics
        if (e > N) e = N;
        if (s > N) s = N;
        for (int i = s + t; i < e; i += 512) g_dagid[i] = d;
        return;
    }
    int bp = blockIdx.x - D;
    int branch = (bp >= nb16) ? 1 : 0;
    int chunk = branch ? bp - nb16 : bp;
    int w = t >> 5, j = t & 31;
    int d = chunk * 16 + w;

    for (int idx = t; idx < 16 * EMB; idx += 512) {
        int dd = chunk * 16 + (idx >> 8);
        sy[idx] = (dd < D) ? y[(size_t)dd * EMB + (idx & 255)] : 0.f;
    }
    const float* Wm = branch ? (prW1 + NH1) : (opW1 + EMB * NH1);
    float a0 = 0.f, a1 = 0.f;
    for (int kc = 0; kc < EMB; kc += 64) {
        __syncthreads();
        for (int idx = t; idx < 64 * NH1; idx += 512) sw[idx] = Wm[(size_t)kc * NH1 + idx];
        __syncthreads();
        const float* yr = sy + w * EMB + kc;
#pragma unroll
        for (int k = 0; k < 64; k += 2) {
            a0 += yr[k + 0] * sw[(k + 0) * NH1 + j];
            a1 += yr[k + 1] * sw[(k + 1) * NH1 + j];
        }
    }
    if (d < D) {
        float a = a0 + a1;
        if (!branch) g_yzop[d * NH1 + j]  = a + g_zop[j];
        else         g_prpre[d * NH1 + j] = a + g_zpr[j];
    }
}

// ================= kernel C: main GEMM (f32x2, dup-x smem) + MLP tail + exp + global sum =================
#define BM 256
#define KC 16
#define SXP2 516   // floats per k-row of duplicated-x tile (2*256 + pad 4)
#define SHP 34     // sh row stride (floats, even for u64 stores)

__global__ void __launch_bounds__(256) k_ops(
    const float* __restrict__ x,  const float* __restrict__ W1,
    const float* __restrict__ W2, const float* __restrict__ b2,
    const float* __restrict__ W3, const float* __restrict__ b3,
    const float* __restrict__ msk, float* __restrict__ out, int N)
{
    // union: phase1 = duplicated x tile  sx2[KC][SXP2]  (33 KB)
    //        phase2 = h1-pre             sh [BM][SHP]   (34.8 KB)
    __shared__ float s_buf[BM * SHP];
    __shared__ float swc[KC * NH1];        // W1 chunk [k][j]
    __shared__ float sw2[NH1 * NH2];
    __shared__ float sb2[NH2], sw3[NH2];
    __shared__ float sb3v;
    __shared__ float swr[8];
    __shared__ int   s_last;

    int tid  = threadIdx.x;
    int w    = tid >> 5;
    int lane = tid & 31;
    int bm   = blockIdx.x * BM;

    if (tid < 16) { sb2[tid] = b2[tid]; sw3[tid] = W3[tid]; }
    if (tid == 16) sb3v = b3[0];
    for (int i = tid; i < NH1 * NH2; i += 256) sw2[i] = W2[i];

    int j0    = (w & 3) * 8;            // warp -> j group (broadcast within warp)
    int rbase = (w >> 2) * 128 + lane;  // strided rows: rbase + {0,32,64,96}

    unsigned long long acc[4][4];
#pragma unroll
    for (int i = 0; i < 4; i++)
#pragma unroll
        for (int p = 0; p < 4; p++) acc[i][p] = 0ull;

    for (int kc = 0; kc < EMB; kc += KC) {
        __syncthreads();
        // stage duplicated x tile: s_buf[k*SXP2 + 2*row {+1}] = x value (twice)
#pragma unroll
        for (int it = 0; it < 4; it++) {
            int fi = it * 256 + tid;
            int row = fi >> 2, kq = fi & 3;
            int n = bm + row;
            float4 v = make_float4(0.f, 0.f, 0.f, 0.f);
            if (n < N) v = *reinterpret_cast<const float4*>(&x[(size_t)n * EMB + kc + kq * 4]);
            float* p0 = &s_buf[(kq * 4 + 0) * SXP2 + 2 * row];
            float* p1 = &s_buf[(kq * 4 + 1) * SXP2 + 2 * row];
            float* p2 = &s_buf[(kq * 4 + 2) * SXP2 + 2 * row];
            float* p3 = &s_buf[(kq * 4 + 3) * SXP2 + 2 * row];
            p0[0] = v.x; p0[1] = v.x;
            p1[0] = v.y; p1[1] = v.y;
            p2[0] = v.z; p2[1] = v.z;
            p3[0] = v.w; p3[1] = v.w;
        }
#pragma unroll
        for (int it = 0; it < 2; it++) {
            int idx = it * 256 + tid;
            swc[idx] = W1[(size_t)kc * NH1 + idx];
        }
        __syncthreads();
#pragma unroll
        for (int k = 0; k < KC; k++) {
            const ulonglong2* wp = reinterpret_cast<const ulonglong2*>(&swc[k * NH1 + j0]);
            ulonglong2 wA = wp[0], wB = wp[1];   // broadcast within warp
            unsigned long long xd[4];
#pragma unroll
            for (int i = 0; i < 4; i++)
                xd[i] = *reinterpret_cast<const unsigned long long*>(
                    &s_buf[k * SXP2 + 2 * (rbase + i * 32)]);   // lane-consecutive, conflict-free
#pragma unroll
            for (int i = 0; i < 4; i++) {
                ffma2(acc[i][0], xd[i], wA.x);
                ffma2(acc[i][1], xd[i], wA.y);
                ffma2(acc[i][2], xd[i], wB.x);
                ffma2(acc[i][3], xd[i], wB.y);
            }
        }
    }
    __syncthreads();
    // stage h1-pre to smem (u64 stores, aligned since SHP even, j0 even)
#pragma unroll
    for (int i = 0; i < 4; i++) {
        int row = rbase + i * 32;
#pragma unroll
        for (int p = 0; p < 4; p++)
            *reinterpret_cast<unsigned long long*>(&s_buf[row * SHP + j0 + 2 * p]) = acc[i][p];
    }
    __syncthreads();

    // ---- tail: 1 row per thread ----
    const unsigned long long* w2_64 = reinterpret_cast<const unsigned long long*>(sw2);
    float bsum = 0.f;
    int n = bm + tid;
    if (n < N) {
        int dag = g_dagid[n];
        const float4* yz4 = reinterpret_cast<const float4*>(&g_yzop[dag * NH1]);
        float h1[NH1];
#pragma unroll
        for (int q = 0; q < 8; q++) {
            float4 v = yz4[q];
            h1[q * 4 + 0] = fmaxf(s_buf[tid * SHP + q * 4 + 0] + v.x, 0.f);
            h1[q * 4 + 1] = fmaxf(s_buf[tid * SHP + q * 4 + 1] + v.y, 0.f);
            h1[q * 4 + 2] = fmaxf(s_buf[tid * SHP + q * 4 + 2] + v.z, 0.f);
            h1[q * 4 + 3] = fmaxf(s_buf[tid * SHP + q * 4 + 3] + v.w, 0.f);
        }
        unsigned long long a2[8];
#pragma unroll
        for (int p = 0; p < 8; p++) a2[p] = pack2(sb2[2 * p], sb2[2 * p + 1]);
#pragma unroll
        for (int j = 0; j < NH1; j++) {
            unsigned long long hd = pack2(h1[j], h1[j]);
#pragma unroll
            for (int p = 0; p < 8; p++) ffma2(a2[p], hd, w2_64[j * 8 + p]);
        }
        float logit = sb3v;
#pragma unroll
        for (int p = 0; p < 8; p++) {
            float2 f = unpack2(a2[p]);
            logit += fmaxf(f.x, 0.f) * sw3[2 * p] + fmaxf(f.y, 0.f) * sw3[2 * p + 1];
        }
        logit -= (1.f - msk[n]) * 1000.f;
        float e = expf(logit);   // logits O(1); masked -> exp(-1000)=0. no max-sub needed
        out[n] = e;
        bsum = e;
    }
    // deterministic block partial sum
#pragma unroll
    for (int off = 16; off; off >>= 1) bsum += __shfl_down_sync(0xffffffffu, bsum, off);
    if (lane == 0) swr[w] = bsum;
    __syncthreads();
    if (tid == 0) {
        float b4 = ((swr[0] + swr[1]) + (swr[2] + swr[3]))
                 + ((swr[4] + swr[5]) + (swr[6] + swr[7]));
        g_partial[blockIdx.x] = b4;
        __threadfence();
        unsigned int prev = atomicAdd(&g_counter, 1u);
        s_last = (prev == gridDim.x - 1) ? 1 : 0;
    }
    __syncthreads();
    if (s_last) {
        __threadfence();
        const volatile float* vp = g_partial;
        float a = 0.f;
        for (int i = tid; i < (int)gridDim.x; i += 256) a += vp[i];
#pragma unroll
        for (int off = 16; off; off >>= 1) a += __shfl_down_sync(0xffffffffu, a, off);
        if (lane == 0) swr[w] = a;
        __syncthreads();
        if (tid == 0)
            g_inv = 1.0f / (((swr[0] + swr[1]) + (swr[2] + swr[3]))
                          + ((swr[4] + swr[5]) + (swr[6] + swr[7])));
    }
}

// ================= kernel E: blocks [0,nbN) normalize; rest = prlvl, 4 dags/block =================
__global__ void __launch_bounds__(256) k_E(
    const float* __restrict__ prW1, const float* __restrict__ prW2,
    const float* __restrict__ prb2, const float* __restrict__ prW3,
    const float* __restrict__ prb3, const float* __restrict__ pmsk,
    float* __restrict__ out, float* __restrict__ outp, int N, int W, int D, int nbN)
{
    int t = threadIdx.x;
    if ((int)blockIdx.x < nbN) {
        float inv = g_inv;
        int i4 = blockIdx.x * 256 + t;
        if (i4 * 4 < N) {
            float4* o4 = reinterpret_cast<float4*>(out);
            float4 v = o4[i4];
            v.x *= inv; v.y *= inv; v.z *= inv; v.w *= inv;
            o4[i4] = v;
        }
        return;
    }
    __shared__ float spre[4 * NH1], sr0[NH1], sW2[NH1 * NH2], sb2[NH2], sW3[NH2];
    __shared__ float sb3v;
    __shared__ float sred[8];
    int pb = blockIdx.x - nbN;       // 4 dags per block
    int dbase = pb * 4;
    int dl = t >> 6, wk = t & 63;
    int lane = t & 31, wrp = t >> 5;
    int d = dbase + dl;

    if (t < 4 * NH1) {
        int dd = dbase + (t >> 5);
        spre[t] = (dd < D) ? g_prpre[dbase * NH1 + t] : 0.f;
    }
    if (t >= 128 && t < 160) sr0[t - 128] = prW1[t - 128];
    for (int i = t; i < NH1 * NH2; i += 256) sW2[i] = prW2[i];
    if (t >= 160 && t < 176) { sb2[t - 160] = prb2[t - 160]; sW3[t - 160] = prW3[t - 160]; }
    if (t == 176) sb3v = prb3[0];
    __syncthreads();

    const unsigned long long* w2_64 = reinterpret_cast<const unsigned long long*>(sW2);
    float l = -1e30f;
    if (d < D && wk < W) {
        float lim = (float)(wk + 1);
        float h1[NH1];
#pragma unroll
        for (int j = 0; j < NH1; j++) h1[j] = fmaxf(spre[dl * NH1 + j] + lim * sr0[j], 0.f);
        unsigned long long a2[8];
#pragma unroll
        for (int p = 0; p < 8; p++) a2[p] = pack2(sb2[2 * p], sb2[2 * p + 1]);
#pragma unroll
        for (int j = 0; j < NH1; j++) {
            unsigned long long hd = pack2(h1[j], h1[j]);
#pragma unroll
            for (int p = 0; p < 8; p++) ffma2(a2[p], hd, w2_64[j * 8 + p]);
        }
        float logit = sb3v;
#pragma unroll
        for (int p = 0; p < 8; p++) {
            float2 f = unpack2(a2[p]);
            logit += fmaxf(f.x, 0.f) * sW3[2 * p] + fmaxf(f.y, 0.f) * sW3[2 * p + 1];
        }
        l = logit - (1.f - pmsk[(size_t)d * W + wk]) * 1000.f;
    }
    // per-dag (2-warp) max
    float m = l;
#pragma unroll
    for (int off = 16; off; off >>= 1) m = fmaxf(m, __shfl_xor_sync(0xffffffffu, m, off));
    if (lane == 0) sred[wrp] = m;
    __syncthreads();
    m = fmaxf(sred[dl * 2], sred[dl * 2 + 1]);
    float e = (d < D && wk < W) ? expf(l - m) : 0.f;
    // per-dag sum
    float s = e;
#pragma unroll
    for (int off = 16; off; off >>= 1) s += __shfl_xor_sync(0xffffffffu, s, off);
    __syncthreads();
    if (lane == 0) sred[wrp] = s;
    __syncthreads();
    s = sred[dl * 2] + sred[dl * 2 + 1];
    if (d < D && wk < W) outp[(size_t)d * W + wk] = e / s;
}

// ================= launch =================
extern "C" void kernel_launch(void* const* d_in, const int* in_sizes, int n_in,
                              void* d_out, int out_size) {
    int ix = 0; long long best = -1;
    for (int i = 0; i < n_in; i++)
        if ((long long)in_sizes[i] > best) { best = in_sizes[i]; ix = i; }

    const int*   num_ops = (const int*)d_in[0];
    const float* x    = (const float*)d_in[ix];
    const float* y    = (const float*)d_in[ix + 1];
    const float* z    = (const float*)d_in[ix + 2];
    const float* omsk = (const float*)d_in[ix + 3];
    const float* pmsk = (const float*)d_in[ix + 4];
    const float* oW1  = (const float*)d_in[ix + 5];
    const float* ob1  = (const float*)d_in[ix + 6];
    const float* oW2  = (const float*)d_in[ix + 7];
    const float* ob2  = (const float*)d_in[ix + 8];
    const float* oW3  = (const float*)d_in[ix + 9];
    const float* ob3  = (const float*)d_in[ix + 10];
    const float* pW1  = (const float*)d_in[ix + 11];
    const float* pb1  = (const float*)d_in[ix + 12];
    const float* pW2  = (const float*)d_in[ix + 13];
    const float* pb2  = (const float*)d_in[ix + 14];
    const float* pW3  = (const float*)d_in[ix + 15];
    const float* pb3  = (const float*)d_in[ix + 16];

    int N = in_sizes[ix] / EMB;
    int D = in_sizes[ix + 1] / EMB;
    int W = in_sizes[ix + 4] / D;

    float* out  = (float*)d_out;
    float* outp = out + N;

    int nb16 = (D + 15) / 16;
    int nb   = (N + BM - 1) / BM;
    int nbN  = (N + 1023) / 1024;
    int DB   = (D + 3) / 4;

    k_A<<<2, 1024>>>(num_ops, z, oW1, ob1, pW1, pb1, D);
    k_B<<<D + 2 * nb16, 512>>>(y, oW1, pW1, D, N, nb16);
    k_ops<<<nb, 256>>>(x, oW1, oW2, ob2, oW3, ob3, omsk, out, N);
    k_E<<<nbN + DB, 256>>>(pW1, pW2, pb2, pW3, pb3, pmsk, out, outp, N, W, D, nbN);
}

// round 4
// speedup vs baseline: 1.1297x; 1.1297x over previous
#include <cuda_runtime.h>
#include <math.h>

#define EMB 256
#define NH1 32
#define NH2 16
#define MAXDAGS 1024
#define MAXOPS  102400

// ---------------- scratch (device globals; no allocation allowed) ----------------
__device__ int   g_offsets[MAXDAGS + 1];
__device__ int   g_dagid[MAXOPS];
__device__ float g_yzop[MAXDAGS * NH1];
__device__ float g_prpre[MAXDAGS * NH1];
__device__ float g_zop[NH1];
__device__ float g_zpr[NH1];
__device__ float g_partial[1024];
__device__ float g_inv;
__device__ unsigned int g_counter;

// ---------------- f32x2 helpers ----------------
__device__ __forceinline__ void ffma2(unsigned long long& d, unsigned long long a, unsigned long long b) {
    asm("fma.rn.f32x2 %0, %1, %2, %0;" : "+l"(d) : "l"(a), "l"(b));
}
__device__ __forceinline__ unsigned long long pack2(float x, float y) {
    unsigned long long r;
    asm("mov.b64 %0, {%1,%2};" : "=l"(r) : "f"(x), "f"(y));
    return r;
}
__device__ __forceinline__ float2 unpack2(unsigned long long v) {
    float2 r;
    asm("mov.b64 {%0,%1}, %2;" : "=f"(r.x), "=f"(r.y) : "l"(v));
    return r;
}

// ================= kernel A: block0 = prefix scan (+counter reset), block1 = z-dots =================
__global__ void __launch_bounds__(1024) k_A(
    const int* __restrict__ num_ops, const float* __restrict__ z,
    const float* __restrict__ opW1, const float* __restrict__ opb1,
    const float* __restrict__ prW1, const float* __restrict__ prb1, int D)
{
    __shared__ int s[1024];
    __shared__ float sz[EMB];
    int t = threadIdx.x;
    if (blockIdx.x == 0) {
        if (t == 0) g_counter = 0u;
        int v = (t < D) ? num_ops[t] : 0;
        s[t] = v;
        __syncthreads();
        for (int off = 1; off < 1024; off <<= 1) {
            int u = (t >= off) ? s[t - off] : 0;
            __syncthreads();
            s[t] += u;
            __syncthreads();
        }
        g_offsets[t + 1] = s[t];
        if (t == 0) g_offsets[0] = 0;
    } else {
        for (int i = t; i < EMB; i += 1024) sz[i] = z[i];
        __syncthreads();
        if (t < 64) {
            int j = t & 31;
            const float* W = (t < 32) ? (opW1 + 2 * EMB * NH1) : (prW1 + (1 + EMB) * NH1);
            float a0 = 0.f, a1 = 0.f, a2 = 0.f, a3 = 0.f;
            for (int k = 0; k < EMB; k += 4) {
                a0 += sz[k + 0] * W[(k + 0) * NH1 + j];
                a1 += sz[k + 1] * W[(k + 1) * NH1 + j];
                a2 += sz[k + 2] * W[(k + 2) * NH1 + j];
                a3 += sz[k + 3] * W[(k + 3) * NH1 + j];
            }
            float a = (a0 + a1) + (a2 + a3);
            if (t < 32) g_zop[j] = a + opb1[j];
            else        g_zpr[j] = a + prb1[j];
        }
    }
}

// ================= kernel B: blocks [0,nbF) = binary-search dag-id fill; rest = per-dag y-dots =================
__global__ void __launch_bounds__(512) k_B(
    const float* __restrict__ y,
    const float* __restrict__ opW1, const float* __restrict__ prW1,
    int D, int N, int nbF, int nb16)
{
    __shared__ float sy[16 * EMB];   // 16 KB (also aliases offsets for fill blocks)
    __shared__ float sw[64 * NH1];   // 8 KB
    int t = threadIdx.x;

    if ((int)blockIdx.x < nbF) {
        int* soff = reinterpret_cast<int*>(sy);
        for (int i = t; i <= D; i += 512) soff[i] = g_offsets[i];
        __syncthreads();
        int i = blockIdx.x * 512 + t;
        if (i < N) {
            // upper_bound: find d with soff[d] <= i < soff[d+1]; clamp (pad-with-last)
            int lo = 0, hi = D;
            while (lo < hi) {
                int mid = (lo + hi) >> 1;
                if (soff[mid + 1] <= i) lo = mid + 1; else hi = mid;
            }
            if (lo >= D) lo = D - 1;
            g_dagid[i] = lo;
        }
        return;
    }
    int bp = blockIdx.x - nbF;
    int branch = (bp >= nb16) ? 1 : 0;
    int chunk = branch ? bp - nb16 : bp;
    int w = t >> 5, j = t & 31;
    int d = chunk * 16 + w;

    for (int idx = t; idx < 16 * EMB; idx += 512) {
        int dd = chunk * 16 + (idx >> 8);
        sy[idx] = (dd < D) ? y[(size_t)dd * EMB + (idx & 255)] : 0.f;
    }
    const float* Wm = branch ? (prW1 + NH1) : (opW1 + EMB * NH1);
    float a0 = 0.f, a1 = 0.f;
    for (int kc = 0; kc < EMB; kc += 64) {
        __syncthreads();
        for (int idx = t; idx < 64 * NH1; idx += 512) sw[idx] = Wm[(size_t)kc * NH1 + idx];
        __syncthreads();
        const float* yr = sy + w * EMB + kc;
#pragma unroll
        for (int k = 0; k < 64; k += 2) {
            a0 += yr[k + 0] * sw[(k + 0) * NH1 + j];
            a1 += yr[k + 1] * sw[(k + 1) * NH1 + j];
        }
    }
    if (d < D) {
        float a = a0 + a1;
        if (!branch) g_yzop[d * NH1 + j]  = a + g_zop[j];
        else         g_prpre[d * NH1 + j] = a + g_zpr[j];
    }
}

// ================= kernel PR: prlvl branch, 8 dags per 512-thread block =================
__global__ void __launch_bounds__(512) k_PR(
    const float* __restrict__ prW1, const float* __restrict__ prW2,
    const float* __restrict__ prb2, const float* __restrict__ prW3,
    const float* __restrict__ prb3, const float* __restrict__ pmsk,
    float* __restrict__ outp, int W, int D)
{
    __shared__ float spre[8 * NH1], sr0[NH1], sW2[NH1 * NH2], sb2[NH2], sW3[NH2];
    __shared__ float sb3v;
    __shared__ float sredm[16], sreds[16];
    int t = threadIdx.x;
    int dbase = blockIdx.x * 8;
    int dl = t >> 6, wk = t & 63;
    int lane = t & 31, wrp = t >> 5;
    int d = dbase + dl;

    if (t < 8 * NH1) {
        int dd = dbase + (t >> 5);
        spre[t] = (dd < D) ? g_prpre[dbase * NH1 + t] : 0.f;
    }
    if (t >= 256 && t < 288) sr0[t - 256] = prW1[t - 256];
    for (int i = t; i < NH1 * NH2; i += 512) sW2[i] = prW2[i];
    if (t >= 288 && t < 304) { sb2[t - 288] = prb2[t - 288]; sW3[t - 288] = prW3[t - 288]; }
    if (t == 304) sb3v = prb3[0];
    __syncthreads();

    const unsigned long long* w2_64 = reinterpret_cast<const unsigned long long*>(sW2);
    float l = -1e30f;
    if (d < D && wk < W) {
        float lim = (float)(wk + 1);
        float h1[NH1];
#pragma unroll
        for (int j = 0; j < NH1; j++) h1[j] = fmaxf(spre[dl * NH1 + j] + lim * sr0[j], 0.f);
        unsigned long long a2[8];
#pragma unroll
        for (int p = 0; p < 8; p++) a2[p] = pack2(sb2[2 * p], sb2[2 * p + 1]);
#pragma unroll
        for (int j = 0; j < NH1; j++) {
            unsigned long long hd = pack2(h1[j], h1[j]);
#pragma unroll
            for (int p = 0; p < 8; p++) ffma2(a2[p], hd, w2_64[j * 8 + p]);
        }
        float logit = sb3v;
#pragma unroll
        for (int p = 0; p < 8; p++) {
            float2 f = unpack2(a2[p]);
            logit += fmaxf(f.x, 0.f) * sW3[2 * p] + fmaxf(f.y, 0.f) * sW3[2 * p + 1];
        }
        l = logit - (1.f - pmsk[(size_t)d * W + wk]) * 1000.f;
    }
    float m = l;
#pragma unroll
    for (int off = 16; off; off >>= 1) m = fmaxf(m, __shfl_xor_sync(0xffffffffu, m, off));
    if (lane == 0) sredm[wrp] = m;
    __syncthreads();
    m = fmaxf(sredm[dl * 2], sredm[dl * 2 + 1]);
    float e = (d < D && wk < W) ? expf(l - m) : 0.f;
    float s = e;
#pragma unroll
    for (int off = 16; off; off >>= 1) s += __shfl_xor_sync(0xffffffffu, s, off);
    if (lane == 0) sreds[wrp] = s;
    __syncthreads();
    s = sreds[dl * 2] + sreds[dl * 2 + 1];
    if (d < D && wk < W) outp[(size_t)d * W + wk] = e / s;
}

// ================= kernel C: main GEMM (dual-k f32x2) + MLP tail + exp + global sum =================
#define BM 128
#define KC 64
#define SXP 66    // x tile row stride (floats, even for LDS.64 / STS.64)
#define SHP 34    // h-pre row stride

__global__ void __launch_bounds__(128) k_ops(
    const float* __restrict__ x,  const float* __restrict__ W1,
    const float* __restrict__ W2, const float* __restrict__ b2,
    const float* __restrict__ W3, const float* __restrict__ b3,
    const float* __restrict__ msk, float* __restrict__ out, int N)
{
    // phase1: x tile row-major [BM][SXP] (33.8 KB); phase2 alias: h-pre [BM][SHP]
    __shared__ float s_buf[BM * SXP];
    __shared__ float swi[(KC / 2) * 64];   // interleaved W1 chunk: [kp][2*j+e]  (8 KB)
    __shared__ float sw2[NH1 * NH2];
    __shared__ float sb2[NH2], sw3[NH2];
    __shared__ float sb3v;
    __shared__ float swr[4];
    __shared__ int   s_last;

    int tid  = threadIdx.x;
    int w    = tid >> 5;
    int lane = tid & 31;
    int bm   = blockIdx.x * BM;
    int j0   = w * 8;     // warp -> 8 j's (broadcast within warp)

    if (tid < 16) { sb2[tid] = b2[tid]; sw3[tid] = W3[tid]; }
    if (tid == 16) sb3v = b3[0];
    for (int i = tid; i < NH1 * NH2; i += 128) sw2[i] = W2[i];

    // acc[i][p]: rows m = lane + 32*i, cols j = j0 + 2p, j0 + 2p + 1... actually
    // acc[i][p] covers column j0+p, lanes of u64 = (even-k partial, odd-k partial)
    unsigned long long acc[4][8];
#pragma unroll
    for (int i = 0; i < 4; i++)
#pragma unroll
        for (int p = 0; p < 8; p++) acc[i][p] = 0ull;

    for (int kc = 0; kc < EMB; kc += KC) {
        __syncthreads();
        // stage x tile row-major via float2 (coalesced LDG.64, aligned STS.64)
#pragma unroll
        for (int it = 0; it < 32; it++) {
            int fi = it * 128 + tid;
            int row = fi >> 5, c2 = fi & 31;
            int n = bm + row;
            float2 v = make_float2(0.f, 0.f);
            if (n < N) v = *reinterpret_cast<const float2*>(&x[(size_t)n * EMB + kc + c2 * 2]);
            *reinterpret_cast<float2*>(&s_buf[row * SXP + c2 * 2]) = v;
        }
        // stage W1 chunk interleaved: swi[kp*64 + 2*j + e] = W1[(kc+2*kp+e)*32 + j]
#pragma unroll
        for (int it = 0; it < 16; it++) {
            int idx = it * 128 + tid;            // 0..2047
            int kp = idx >> 6, r = idx & 63;
            int e = r & 1, j = r >> 1;
            swi[kp * 64 + 2 * j + e] = W1[(size_t)(kc + 2 * kp + e) * NH1 + j];
        }
        __syncthreads();
#pragma unroll 8
        for (int kp = 0; kp < KC / 2; kp++) {
            unsigned long long xk[4];
#pragma unroll
            for (int i = 0; i < 4; i++)
                xk[i] = *reinterpret_cast<const unsigned long long*>(
                    &s_buf[(lane + 32 * i) * SXP + 2 * kp]);
            const ulonglong2* wp = reinterpret_cast<const ulonglong2*>(&swi[kp * 64 + 2 * j0]);
            ulonglong2 wa = wp[0], wb = wp[1], wc = wp[2], wd = wp[3];  // 8 (w_even,w_odd) pairs
#pragma unroll
            for (int i = 0; i < 4; i++) {
                ffma2(acc[i][0], xk[i], wa.x);
                ffma2(acc[i][1], xk[i], wa.y);
                ffma2(acc[i][2], xk[i], wb.x);
                ffma2(acc[i][3], xk[i], wb.y);
                ffma2(acc[i][4], xk[i], wc.x);
                ffma2(acc[i][5], xk[i], wc.y);
                ffma2(acc[i][6], xk[i], wd.x);
                ffma2(acc[i][7], xk[i], wd.y);
            }
        }
    }
    __syncthreads();
    // reduce lanes (even+odd k) and stage h-pre
#pragma unroll
    for (int i = 0; i < 4; i++) {
        int row = lane + 32 * i;
#pragma unroll
        for (int p = 0; p < 8; p++) {
            float2 f = unpack2(acc[i][p]);
            s_buf[row * SHP + j0 + p] = f.x + f.y;
        }
    }
    __syncthreads();

    // ---- tail: 1 row per thread ----
    const unsigned long long* w2_64 = reinterpret_cast<const unsigned long long*>(sw2);
    float bsum = 0.f;
    int n = bm + tid;
    if (n < N) {
        int dag = g_dagid[n];
        const float4* yz4 = reinterpret_cast<const float4*>(&g_yzop[dag * NH1]);
        float h1[NH1];
#pragma unroll
        for (int q = 0; q < 8; q++) {
            float4 v = yz4[q];
            h1[q * 4 + 0] = fmaxf(s_buf[tid * SHP + q * 4 + 0] + v.x, 0.f);
            h1[q * 4 + 1] = fmaxf(s_buf[tid * SHP + q * 4 + 1] + v.y, 0.f);
            h1[q * 4 + 2] = fmaxf(s_buf[tid * SHP + q * 4 + 2] + v.z, 0.f);
            h1[q * 4 + 3] = fmaxf(s_buf[tid * SHP + q * 4 + 3] + v.w, 0.f);
        }
        unsigned long long a2[8];
#pragma unroll
        for (int p = 0; p < 8; p++) a2[p] = pack2(sb2[2 * p], sb2[2 * p + 1]);
#pragma unroll
        for (int j = 0; j < NH1; j++) {
            unsigned long long hd = pack2(h1[j], h1[j]);
#pragma unroll
            for (int p = 0; p < 8; p++) ffma2(a2[p], hd, w2_64[j * 8 + p]);
        }
        float logit = sb3v;
#pragma unroll
        for (int p = 0; p < 8; p++) {
            float2 f = unpack2(a2[p]);
            logit += fmaxf(f.x, 0.f) * sw3[2 * p] + fmaxf(f.y, 0.f) * sw3[2 * p + 1];
        }
        logit -= (1.f - msk[n]) * 1000.f;
        float e = expf(logit);   // logits O(1); masked -> exp(-1000)=0. no max-sub needed
        out[n] = e;
        bsum = e;
    }
    // deterministic block partial sum
#pragma unroll
    for (int off = 16; off; off >>= 1) bsum += __shfl_down_sync(0xffffffffu, bsum, off);
    if (lane == 0) swr[w] = bsum;
    __syncthreads();
    if (tid == 0) {
        g_partial[blockIdx.x] = (swr[0] + swr[1]) + (swr[2] + swr[3]);
        __threadfence();
        unsigned int prev = atomicAdd(&g_counter, 1u);
        s_last = (prev == gridDim.x - 1) ? 1 : 0;
    }
    __syncthreads();
    if (s_last) {
        __threadfence();
        const volatile float* vp = g_partial;
        float a = 0.f;
        for (int i = tid; i < (int)gridDim.x; i += 128) a += vp[i];
#pragma unroll
        for (int off = 16; off; off >>= 1) a += __shfl_down_sync(0xffffffffu, a, off);
        if (lane == 0) swr[w] = a;
        __syncthreads();
        if (tid == 0) g_inv = 1.0f / ((swr[0] + swr[1]) + (swr[2] + swr[3]));
    }
}

// ================= kernel N: normalize ops output =================
__global__ void __launch_bounds__(1024) k_norm(float* __restrict__ out, int N) {
    float inv = g_inv;
    int i4 = blockIdx.x * 1024 + threadIdx.x;
    if (i4 * 4 < N) {
        float4* o4 = reinterpret_cast<float4*>(out);
        float4 v = o4[i4];
        v.x *= inv; v.y *= inv; v.z *= inv; v.w *= inv;
        o4[i4] = v;
    }
}

// ================= launch =================
extern "C" void kernel_launch(void* const* d_in, const int* in_sizes, int n_in,
                              void* d_out, int out_size) {
    int ix = 0; long long best = -1;
    for (int i = 0; i < n_in; i++)
        if ((long long)in_sizes[i] > best) { best = in_sizes[i]; ix = i; }

    const int*   num_ops = (const int*)d_in[0];
    const float* x    = (const float*)d_in[ix];
    const float* y    = (const float*)d_in[ix + 1];
    const float* z    = (const float*)d_in[ix + 2];
    const float* omsk = (const float*)d_in[ix + 3];
    const float* pmsk = (const float*)d_in[ix + 4];
    const float* oW1  = (const float*)d_in[ix + 5];
    const float* ob1  = (const float*)d_in[ix + 6];
    const float* oW2  = (const float*)d_in[ix + 7];
    const float* ob2  = (const float*)d_in[ix + 8];
    const float* oW3  = (const float*)d_in[ix + 9];
    const float* ob3  = (const float*)d_in[ix + 10];
    const float* pW1  = (const float*)d_in[ix + 11];
    const float* pb1  = (const float*)d_in[ix + 12];
    const float* pW2  = (const float*)d_in[ix + 13];
    const float* pb2  = (const float*)d_in[ix + 14];
    const float* pW3  = (const float*)d_in[ix + 15];
    const float* pb3  = (const float*)d_in[ix + 16];

    int N = in_sizes[ix] / EMB;
    int D = in_sizes[ix + 1] / EMB;
    int W = in_sizes[ix + 4] / D;

    float* out  = (float*)d_out;
    float* outp = out + N;

    int nbF  = (N + 511) / 512;
    int nb16 = (D + 15) / 16;
    int nb   = (N + BM - 1) / BM;
    int nbPR = (D + 7) / 8;
    int nbNm = (N + 4095) / 4096;

    k_A<<<2, 1024>>>(num_ops, z, oW1, ob1, pW1, pb1, D);
    k_B<<<nbF + 2 * nb16, 512>>>(y, oW1, pW1, D, N, nbF, nb16);
    k_PR<<<nbPR, 512>>>(pW1, pW2, pb2, pW3, pb3, pmsk, outp, W, D);
    k_ops<<<nb, 128>>>(x, oW1, oW2, ob2, oW3, ob3, omsk, out, N);
    k_norm<<<nbNm, 1024>>>(out, N);
}